// round 2
// baseline (speedup 1.0000x reference)
#include <cuda_runtime.h>

#define NN 100000
#define EPS 1e-5f

typedef unsigned long long ull;

// ---- scratch (device globals; 256B-aligned for v4 red / float4) ----
__device__ __align__(256) float g_agg1[NN * 128];   // sum of x[src] per dst
__device__ __align__(256) float g_h   [NN * 128];   // layer-1 output (post BN+ReLU)
__device__ __align__(256) float g_y2  [NN * 128];   // [ h@W2l^T (64) | h@W2r^T (64) ]
__device__ __align__(256) float g_agg2[NN * 64];    // sum of y2l[src] per dst
__device__ __align__(256) float g_cnt [NN];         // in-degree (float)

// ---- packed f32x2 helpers (Blackwell dual-rate fp32) ----
__device__ __forceinline__ ull pack2(float lo, float hi) {
    ull r; asm("mov.b64 %0, {%1, %2};" : "=l"(r) : "f"(lo), "f"(hi)); return r;
}
__device__ __forceinline__ void unpack2(ull v, float& lo, float& hi) {
    asm("mov.b64 {%0, %1}, %2;" : "=f"(lo), "=f"(hi) : "l"(v));
}
__device__ __forceinline__ ull ffma2(ull a, ull b, ull c) {
    ull d; asm("fma.rn.f32x2 %0, %1, %2, %3;" : "=l"(d) : "l"(a), "l"(b), "l"(c)); return d;
}

// ---------------------------------------------------------------------------
__global__ void zero_kernel() {
    int idx = blockIdx.x * blockDim.x + threadIdx.x;
    int stride = gridDim.x * blockDim.x;
    float4 z = make_float4(0.f, 0.f, 0.f, 0.f);
    float4* a1 = (float4*)g_agg1;
    float4* a2 = (float4*)g_agg2;
    float4* c  = (float4*)g_cnt;
    for (int i = idx; i < NN * 32; i += stride) a1[i] = z;
    for (int i = idx; i < NN * 16; i += stride) a2[i] = z;
    for (int i = idx; i < NN / 4;  i += stride) c[i]  = z;
}

// ---------------------------------------------------------------------------
// Layer-1 aggregation: warp per edge; gather x[src] (128f), v4-red into agg1[dst].
// Degree count fused on lane 0. NOTE: edge indices are int32 (JAX x64 disabled).
__global__ void agg1_kernel(const int* __restrict__ src,
                            const int* __restrict__ dst,
                            const float* __restrict__ x, int E) {
    int w = (blockIdx.x * blockDim.x + threadIdx.x) >> 5;
    if (w >= E) return;
    int lane = threadIdx.x & 31;
    int s = __ldg(src + w);
    int d = __ldg(dst + w);
    float4 v = __ldg((const float4*)x + (long long)s * 32 + lane);
    float* p = g_agg1 + (long long)d * 128 + lane * 4;
    asm volatile("red.global.add.v4.f32 [%0], {%1, %2, %3, %4};"
                 :: "l"(p), "f"(v.x), "f"(v.y), "f"(v.z), "f"(v.w) : "memory");
    if (lane == 0) atomicAdd(&g_cnt[d], 1.f);
}

// ---------------------------------------------------------------------------
// Layer-2 aggregation (transform-first): aggregate only the 64-dim y2l half.
__global__ void agg2_kernel(const int* __restrict__ src,
                            const int* __restrict__ dst, int E) {
    int w = (blockIdx.x * blockDim.x + threadIdx.x) >> 5;
    if (w >= E) return;
    int lane = threadIdx.x & 31;
    int s = __ldg(src + w);
    int d = __ldg(dst + w);
    float2 v = *(const float2*)(g_y2 + (long long)s * 128 + lane * 2);
    float* p = g_agg2 + (long long)d * 64 + lane * 2;
    asm volatile("red.global.add.v2.f32 [%0], {%1, %2};"
                 :: "l"(p), "f"(v.x), "f"(v.y) : "memory");
}

// ---------------------------------------------------------------------------
// GEMM1: h = ReLU(BN(mean@W1l^T + b1l + x@W1r^T))
// A = [agg1*inv | x] (64 rows, K=256), W = [W1l ; W1r] k-major in smem,
// BN scale folded into weight columns, BN shift folded into bias.
#define WS_STRIDE 132
#define SMEM1_FLOATS (64*256 + 256*WS_STRIDE + 128 + 128 + 64)
#define SMEM1_BYTES  (SMEM1_FLOATS * 4)
#define SMEM2_FLOATS (64*128 + 128*WS_STRIDE)
#define SMEM2_BYTES  (SMEM2_FLOATS * 4)

__global__ void __launch_bounds__(512, 1) gemm1_kernel(
    const float* __restrict__ x, const float* __restrict__ W1l,
    const float* __restrict__ b1l, const float* __restrict__ W1r,
    const float* __restrict__ gamma, const float* __restrict__ beta,
    const float* __restrict__ rmean, const float* __restrict__ rvar)
{
    extern __shared__ float sm[];
    float* As   = sm;                        // [64][256]
    float* Ws   = As + 64 * 256;             // [256][WS_STRIDE]
    float* gp   = Ws + 256 * WS_STRIDE;      // [128]
    float* bias = gp + 128;                  // [128]
    float* inv  = bias + 128;                // [64]

    int tid = threadIdx.x;
    int g0 = blockIdx.x * 64;

    if (tid < 128) {
        float g = gamma[tid] * rsqrtf(rvar[tid] + EPS);
        gp[tid] = g;
        bias[tid] = (b1l[tid] - rmean[tid]) * g + beta[tid];
    } else if (tid < 192) {
        int r = tid - 128;
        int row = g0 + r;
        float c = (row < NN) ? g_cnt[row] : 1.f;
        inv[r] = 1.f / fmaxf(c, 1.f);
    }
    __syncthreads();

    // weights: Ws[k][j] = (k<128 ? W1l[j][k] : W1r[j][k-128]) * gp[j]
    for (int idx = tid; idx < 256 * 128; idx += 512) {
        int j = idx >> 8;
        int k = idx & 255;
        float w = (k < 128) ? W1l[j * 128 + k] : W1r[j * 128 + (k - 128)];
        Ws[k * WS_STRIDE + j] = w * gp[j];
    }
    // A tile: [mean | x]
    for (int f4 = tid; f4 < 64 * 64; f4 += 512) {
        int r = f4 >> 6;
        int kq = f4 & 63;
        int row = g0 + r;
        float4 v = make_float4(0.f, 0.f, 0.f, 0.f);
        if (row < NN) {
            if (kq < 32) {
                v = *(const float4*)(g_agg1 + (long long)row * 128 + kq * 4);
                float s = inv[r];
                v.x *= s; v.y *= s; v.z *= s; v.w *= s;
            } else {
                v = *(const float4*)(x + (long long)row * 128 + (kq - 32) * 4);
            }
        }
        *(float4*)(As + r * 256 + kq * 4) = v;
    }
    __syncthreads();

    int c4 = (tid & 31) * 4;     // 4 output cols
    int r0 = (tid >> 5) * 4;     // 4 rows
    ull acc01[4] = {0ULL, 0ULL, 0ULL, 0ULL};
    ull acc23[4] = {0ULL, 0ULL, 0ULL, 0ULL};
    #pragma unroll 4
    for (int k = 0; k < 256; k++) {
        float4 w = *(const float4*)(Ws + k * WS_STRIDE + c4);
        ull w01 = pack2(w.x, w.y);
        ull w23 = pack2(w.z, w.w);
        #pragma unroll
        for (int i = 0; i < 4; i++) {
            float a = As[(r0 + i) * 256 + k];
            ull aa = pack2(a, a);
            acc01[i] = ffma2(aa, w01, acc01[i]);
            acc23[i] = ffma2(aa, w23, acc23[i]);
        }
    }
    float b0 = bias[c4], b1 = bias[c4 + 1], b2 = bias[c4 + 2], b3 = bias[c4 + 3];
    #pragma unroll
    for (int i = 0; i < 4; i++) {
        int row = g0 + r0 + i;
        if (row < NN) {
            float o0, o1, o2, o3;
            unpack2(acc01[i], o0, o1);
            unpack2(acc23[i], o2, o3);
            float4 o = make_float4(fmaxf(o0 + b0, 0.f), fmaxf(o1 + b1, 0.f),
                                   fmaxf(o2 + b2, 0.f), fmaxf(o3 + b3, 0.f));
            *(float4*)(g_h + (long long)row * 128 + c4) = o;
        }
    }
}

// ---------------------------------------------------------------------------
// GEMM2: y2 = h @ [W2l ; W2r]^T  ([N,128]@[128,128]); cols 0..63 = y2l, 64..127 = y2r
__global__ void __launch_bounds__(512, 1) gemm2_kernel(
    const float* __restrict__ W2l, const float* __restrict__ W2r)
{
    extern __shared__ float sm[];
    float* As = sm;               // [64][128]
    float* Ws = As + 64 * 128;    // [128][WS_STRIDE]

    int tid = threadIdx.x;
    int g0 = blockIdx.x * 64;

    for (int idx = tid; idx < 128 * 128; idx += 512) {
        int j = idx >> 7;
        int k = idx & 127;
        float w = (j < 64) ? W2l[j * 128 + k] : W2r[(j - 64) * 128 + k];
        Ws[k * WS_STRIDE + j] = w;
    }
    for (int f4 = tid; f4 < 64 * 32; f4 += 512) {
        int r = f4 >> 5;
        int kq = f4 & 31;
        int row = g0 + r;
        float4 v = make_float4(0.f, 0.f, 0.f, 0.f);
        if (row < NN) v = *(const float4*)(g_h + (long long)row * 128 + kq * 4);
        *(float4*)(As + r * 128 + kq * 4) = v;
    }
    __syncthreads();

    int c4 = (tid & 31) * 4;
    int r0 = (tid >> 5) * 4;
    ull acc01[4] = {0ULL, 0ULL, 0ULL, 0ULL};
    ull acc23[4] = {0ULL, 0ULL, 0ULL, 0ULL};
    #pragma unroll 4
    for (int k = 0; k < 128; k++) {
        float4 w = *(const float4*)(Ws + k * WS_STRIDE + c4);
        ull w01 = pack2(w.x, w.y);
        ull w23 = pack2(w.z, w.w);
        #pragma unroll
        for (int i = 0; i < 4; i++) {
            float a = As[(r0 + i) * 128 + k];
            ull aa = pack2(a, a);
            acc01[i] = ffma2(aa, w01, acc01[i]);
            acc23[i] = ffma2(aa, w23, acc23[i]);
        }
    }
    #pragma unroll
    for (int i = 0; i < 4; i++) {
        int row = g0 + r0 + i;
        if (row < NN) {
            float o0, o1, o2, o3;
            unpack2(acc01[i], o0, o1);
            unpack2(acc23[i], o2, o3);
            *(float4*)(g_y2 + (long long)row * 128 + c4) = make_float4(o0, o1, o2, o3);
        }
    }
}

// ---------------------------------------------------------------------------
// out[i][j] = agg2[i][j]/max(cnt,1) + b2l[j] + y2r[i][j]
__global__ void epi_kernel(const float* __restrict__ b2l, float* __restrict__ out) {
    int idx = blockIdx.x * blockDim.x + threadIdx.x;
    if (idx >= NN * 64) return;
    int i = idx >> 6;
    int j = idx & 63;
    float invc = 1.f / fmaxf(g_cnt[i], 1.f);
    out[idx] = g_agg2[idx] * invc + b2l[j] + g_y2[(long long)i * 128 + 64 + j];
}

// ---------------------------------------------------------------------------
extern "C" void kernel_launch(void* const* d_in, const int* in_sizes, int n_in,
                              void* d_out, int out_size) {
    const float* x     = (const float*)d_in[0];
    const int*   ei    = (const int*)d_in[1];     // int32! (JAX x64 disabled)
    const float* W1l   = (const float*)d_in[2];
    const float* b1l   = (const float*)d_in[3];
    const float* W1r   = (const float*)d_in[4];
    const float* gamma = (const float*)d_in[5];
    const float* beta  = (const float*)d_in[6];
    const float* rmean = (const float*)d_in[7];
    const float* rvar  = (const float*)d_in[8];
    const float* W2l   = (const float*)d_in[9];
    const float* b2l   = (const float*)d_in[10];
    const float* W2r   = (const float*)d_in[11];
    float* out = (float*)d_out;

    int E = in_sizes[1] / 2;
    const int* src = ei;
    const int* dst = ei + E;

    cudaFuncSetAttribute(gemm1_kernel, cudaFuncAttributeMaxDynamicSharedMemorySize, SMEM1_BYTES);
    cudaFuncSetAttribute(gemm2_kernel, cudaFuncAttributeMaxDynamicSharedMemorySize, SMEM2_BYTES);

    zero_kernel<<<1024, 256>>>();

    int aggBlocks = (int)(((long long)E * 32 + 255) / 256);
    agg1_kernel<<<aggBlocks, 256>>>(src, dst, x, E);

    int gemmBlocks = (NN + 63) / 64;
    gemm1_kernel<<<gemmBlocks, 512, SMEM1_BYTES>>>(x, W1l, b1l, W1r, gamma, beta, rmean, rvar);
    gemm2_kernel<<<gemmBlocks, 512, SMEM2_BYTES>>>(W2l, W2r);

    agg2_kernel<<<aggBlocks, 256>>>(src, dst, E);

    epi_kernel<<<(NN * 64 + 255) / 256, 256>>>(b2l, out);
}

// round 3
// speedup vs baseline: 1.4437x; 1.4437x over previous
#include <cuda_runtime.h>

#define NN 100000
#define EMAX 1600000
#define EPS 1e-5f
#define NB ((NN + 1023) >> 10)     // 98 scan blocks

typedef unsigned long long ull;

// ---- scratch (device globals) ----
__device__ __align__(256) float g_agg1[NN * 128];   // mean-aggregated x per dst
__device__ __align__(256) float g_h   [NN * 128];   // layer-1 output (post BN+ReLU)
__device__ __align__(256) float g_y2  [NN * 128];   // [ h@W2l^T (64) | h@W2r^T (64) ]
__device__ int g_cnt_i[NN];
__device__ int g_off[NN + 1];
__device__ int g_cur[NN];
__device__ int g_bsum[NB];
__device__ int g_ssrc[EMAX];

// ---- packed f32x2 helpers ----
__device__ __forceinline__ ull pack2(float lo, float hi) {
    ull r; asm("mov.b64 %0, {%1, %2};" : "=l"(r) : "f"(lo), "f"(hi)); return r;
}
__device__ __forceinline__ void unpack2(ull v, float& lo, float& hi) {
    asm("mov.b64 {%0, %1}, %2;" : "=f"(lo), "=f"(hi) : "l"(v));
}
__device__ __forceinline__ ull ffma2(ull a, ull b, ull c) {
    ull d; asm("fma.rn.f32x2 %0, %1, %2, %3;" : "=l"(d) : "l"(a), "l"(b), "l"(c)); return d;
}

// ===========================================================================
// CSR build: zero hist -> hist -> scan (3 kernels) -> fill
// ===========================================================================
__global__ void zero_cnt_kernel() {
    int i = blockIdx.x * blockDim.x + threadIdx.x;
    if (i < NN) g_cnt_i[i] = 0;
}

__global__ void hist_kernel(const int* __restrict__ dst, int E) {
    int e = blockIdx.x * blockDim.x + threadIdx.x;
    if (e < E) atomicAdd(&g_cnt_i[dst[e]], 1);
}

__global__ void scan1_kernel() {
    __shared__ int sm[1024];
    int tid = threadIdx.x;
    int i = blockIdx.x * 1024 + tid;
    int v = (i < NN) ? g_cnt_i[i] : 0;
    sm[tid] = v;
    __syncthreads();
    for (int off = 1; off < 1024; off <<= 1) {
        int t = (tid >= off) ? sm[tid - off] : 0;
        __syncthreads();
        sm[tid] += t;
        __syncthreads();
    }
    if (i < NN) g_off[i] = sm[tid] - v;                // exclusive within block
    if (tid == 1023) g_bsum[blockIdx.x] = sm[1023];    // block total
}

__global__ void scan2_kernel() {
    __shared__ int sm[128];
    int tid = threadIdx.x;
    int v = (tid < NB) ? g_bsum[tid] : 0;
    sm[tid] = v;
    __syncthreads();
    for (int off = 1; off < 128; off <<= 1) {
        int t = (tid >= off) ? sm[tid - off] : 0;
        __syncthreads();
        sm[tid] += t;
        __syncthreads();
    }
    if (tid < NB) g_bsum[tid] = sm[tid] - v;           // exclusive block prefix
}

__global__ void scan3_kernel(int E) {
    int i = blockIdx.x * blockDim.x + threadIdx.x;
    if (i < NN) {
        int o = g_off[i] + g_bsum[i >> 10];
        g_off[i] = o;
        g_cur[i] = o;
    }
    if (i == 0) g_off[NN] = E;
}

__global__ void fill_kernel(const int* __restrict__ src,
                            const int* __restrict__ dst, int E) {
    int e = blockIdx.x * blockDim.x + threadIdx.x;
    if (e >= E) return;
    int p = atomicAdd(&g_cur[dst[e]], 1);
    g_ssrc[p] = src[e];
}

// ===========================================================================
// agg1: warp per dst, gather x rows over CSR list, write MEAN (no atomics)
// ===========================================================================
__global__ void __launch_bounds__(256) agg1_kernel(const float* __restrict__ x) {
    int w = (blockIdx.x * 256 + threadIdx.x) >> 5;
    if (w >= NN) return;
    int lane = threadIdx.x & 31;
    int beg = g_off[w], end = g_off[w + 1];
    float ax = 0.f, ay = 0.f, az = 0.f, aw = 0.f;
    int e = beg;
    for (; e + 2 <= end; e += 2) {
        int s0 = __ldg(g_ssrc + e);
        int s1 = __ldg(g_ssrc + e + 1);
        float4 v0 = __ldg((const float4*)x + (long long)s0 * 32 + lane);
        float4 v1 = __ldg((const float4*)x + (long long)s1 * 32 + lane);
        ax += v0.x; ay += v0.y; az += v0.z; aw += v0.w;
        ax += v1.x; ay += v1.y; az += v1.z; aw += v1.w;
    }
    if (e < end) {
        int s0 = __ldg(g_ssrc + e);
        float4 v0 = __ldg((const float4*)x + (long long)s0 * 32 + lane);
        ax += v0.x; ay += v0.y; az += v0.z; aw += v0.w;
    }
    float inv = 1.f / (float)max(end - beg, 1);
    float4 o = make_float4(ax * inv, ay * inv, az * inv, aw * inv);
    *((float4*)(g_agg1 + (long long)w * 128 + lane * 4)) = o;
}

// ===========================================================================
// agg2 + epilogue fused: out[d] = mean_agg(y2l) + b2l + y2r[d]
// ===========================================================================
__global__ void __launch_bounds__(256) agg2_kernel(const float* __restrict__ b2l,
                                                   float* __restrict__ out) {
    int w = (blockIdx.x * 256 + threadIdx.x) >> 5;
    if (w >= NN) return;
    int lane = threadIdx.x & 31;
    int beg = g_off[w], end = g_off[w + 1];
    float ax = 0.f, ay = 0.f;
    int e = beg;
    for (; e + 2 <= end; e += 2) {
        int s0 = __ldg(g_ssrc + e);
        int s1 = __ldg(g_ssrc + e + 1);
        float2 v0 = *(const float2*)(g_y2 + (long long)s0 * 128 + lane * 2);
        float2 v1 = *(const float2*)(g_y2 + (long long)s1 * 128 + lane * 2);
        ax += v0.x + v1.x; ay += v0.y + v1.y;
    }
    if (e < end) {
        int s0 = __ldg(g_ssrc + e);
        float2 v0 = *(const float2*)(g_y2 + (long long)s0 * 128 + lane * 2);
        ax += v0.x; ay += v0.y;
    }
    float inv = 1.f / (float)max(end - beg, 1);
    int j = lane * 2;
    float2 yr = *(const float2*)(g_y2 + (long long)w * 128 + 64 + j);
    float2 o = make_float2(ax * inv + __ldg(b2l + j)     + yr.x,
                           ay * inv + __ldg(b2l + j + 1) + yr.y);
    *(float2*)(out + (long long)w * 64 + j) = o;
}

// ===========================================================================
// GEMMs: 64x128 tile, 256 threads, per-thread 4 rows x 8 cols, K-chunk 128.
// Ws k-major [128][132]; As row-major [64][132]. W loaded as ull pairs.
// ===========================================================================
#define TS 132
#define GEMM1_SMEM ((64*TS + 128*TS + 128 + 128) * 4)
#define GEMM2_SMEM ((64*TS + 128*TS) * 4)

struct Acc { ull a[4][4]; };   // [row][colpair]

__device__ __forceinline__ void mainloop(const float* As, const float* Ws,
                                         int r0, int c0, Acc& A) {
    #pragma unroll 4
    for (int k = 0; k < 128; k++) {
        const float* wr = Ws + k * TS + c0;
        ulonglong2 wA = *(const ulonglong2*)(wr);
        ulonglong2 wB = *(const ulonglong2*)(wr + 4);
        #pragma unroll
        for (int i = 0; i < 4; i++) {
            float a = As[(r0 + i) * TS + k];
            ull aa = pack2(a, a);
            A.a[i][0] = ffma2(aa, wA.x, A.a[i][0]);
            A.a[i][1] = ffma2(aa, wA.y, A.a[i][1]);
            A.a[i][2] = ffma2(aa, wB.x, A.a[i][2]);
            A.a[i][3] = ffma2(aa, wB.y, A.a[i][3]);
        }
    }
}

__device__ __forceinline__ void load_A_tile(float* As, const float* __restrict__ src,
                                            int g0, int tid) {
    // 64 rows x 32 float4; warp = one row, 32 kq -> coalesced read, conflict-free store
    #pragma unroll
    for (int it = 0; it < 8; it++) {
        int idx = it * 256 + tid;
        int row = idx >> 5;
        int kq = idx & 31;
        int grow = g0 + row;
        float4 v = make_float4(0.f, 0.f, 0.f, 0.f);
        if (grow < NN) v = __ldg((const float4*)src + (long long)grow * 32 + kq);
        *(float4*)(As + row * TS + kq * 4) = v;
    }
}

__global__ void __launch_bounds__(256, 2) gemm1_kernel(
    const float* __restrict__ x, const float* __restrict__ W1l,
    const float* __restrict__ b1l, const float* __restrict__ W1r,
    const float* __restrict__ gamma, const float* __restrict__ beta,
    const float* __restrict__ rmean, const float* __restrict__ rvar)
{
    extern __shared__ float sm[];
    float* As   = sm;              // [64][TS]
    float* Ws   = As + 64 * TS;    // [128][TS]
    float* gp   = Ws + 128 * TS;   // [128]
    float* bias = gp + 128;        // [128]

    int tid = threadIdx.x;
    int g0 = blockIdx.x * 64;

    if (tid < 128) {
        float g = gamma[tid] * rsqrtf(rvar[tid] + EPS);
        gp[tid] = g;
        bias[tid] = (b1l[tid] - rmean[tid]) * g + beta[tid];
    }
    __syncthreads();

    int c0 = (tid & 15) * 8;
    int r0 = (tid >> 4) * 4;
    Acc acc;
    #pragma unroll
    for (int i = 0; i < 4; i++)
        #pragma unroll
        for (int j = 0; j < 4; j++) acc.a[i][j] = 0ULL;

    #pragma unroll
    for (int phase = 0; phase < 2; phase++) {
        const float* Asrc = phase ? x : g_agg1;
        const float* Wsrc = phase ? W1r : W1l;
        // Ws[k][j] = Wsrc[j][k] * gp[j]
        #pragma unroll
        for (int it = 0; it < 64; it++) {
            int idx = it * 256 + tid;
            int j = idx >> 7;
            int k = idx & 127;
            Ws[k * TS + j] = __ldg(Wsrc + j * 128 + k) * gp[j];
        }
        load_A_tile(As, Asrc, g0, tid);
        __syncthreads();
        mainloop(As, Ws, r0, c0, acc);
        __syncthreads();
    }

    #pragma unroll
    for (int i = 0; i < 4; i++) {
        int row = g0 + r0 + i;
        if (row >= NN) break;
        float o[8];
        unpack2(acc.a[i][0], o[0], o[1]);
        unpack2(acc.a[i][1], o[2], o[3]);
        unpack2(acc.a[i][2], o[4], o[5]);
        unpack2(acc.a[i][3], o[6], o[7]);
        float* outp = g_h + (long long)row * 128 + c0;
        float4 v0 = make_float4(fmaxf(o[0] + bias[c0+0], 0.f), fmaxf(o[1] + bias[c0+1], 0.f),
                                fmaxf(o[2] + bias[c0+2], 0.f), fmaxf(o[3] + bias[c0+3], 0.f));
        float4 v1 = make_float4(fmaxf(o[4] + bias[c0+4], 0.f), fmaxf(o[5] + bias[c0+5], 0.f),
                                fmaxf(o[6] + bias[c0+6], 0.f), fmaxf(o[7] + bias[c0+7], 0.f));
        *(float4*)(outp) = v0;
        *(float4*)(outp + 4) = v1;
    }
}

__global__ void __launch_bounds__(256, 2) gemm2_kernel(
    const float* __restrict__ W2l, const float* __restrict__ W2r)
{
    extern __shared__ float sm[];
    float* As = sm;                // [64][TS]
    float* Ws = As + 64 * TS;      // [128][TS]

    int tid = threadIdx.x;
    int g0 = blockIdx.x * 64;

    // Ws[k][j] = (j<64 ? W2l[j][k] : W2r[j-64][k])
    #pragma unroll
    for (int it = 0; it < 64; it++) {
        int idx = it * 256 + tid;
        int j = idx >> 7;
        int k = idx & 127;
        float w = (j < 64) ? __ldg(W2l + j * 128 + k) : __ldg(W2r + (j - 64) * 128 + k);
        Ws[k * TS + j] = w;
    }
    load_A_tile(As, g_h, g0, tid);
    __syncthreads();

    int c0 = (tid & 15) * 8;
    int r0 = (tid >> 4) * 4;
    Acc acc;
    #pragma unroll
    for (int i = 0; i < 4; i++)
        #pragma unroll
        for (int j = 0; j < 4; j++) acc.a[i][j] = 0ULL;

    mainloop(As, Ws, r0, c0, acc);

    #pragma unroll
    for (int i = 0; i < 4; i++) {
        int row = g0 + r0 + i;
        if (row >= NN) break;
        float o[8];
        unpack2(acc.a[i][0], o[0], o[1]);
        unpack2(acc.a[i][1], o[2], o[3]);
        unpack2(acc.a[i][2], o[4], o[5]);
        unpack2(acc.a[i][3], o[6], o[7]);
        float* outp = g_y2 + (long long)row * 128 + c0;
        *(float4*)(outp)     = make_float4(o[0], o[1], o[2], o[3]);
        *(float4*)(outp + 4) = make_float4(o[4], o[5], o[6], o[7]);
    }
}

// ===========================================================================
extern "C" void kernel_launch(void* const* d_in, const int* in_sizes, int n_in,
                              void* d_out, int out_size) {
    const float* x     = (const float*)d_in[0];
    const int*   ei    = (const int*)d_in[1];     // int32 (JAX x64 disabled)
    const float* W1l   = (const float*)d_in[2];
    const float* b1l   = (const float*)d_in[3];
    const float* W1r   = (const float*)d_in[4];
    const float* gamma = (const float*)d_in[5];
    const float* beta  = (const float*)d_in[6];
    const float* rmean = (const float*)d_in[7];
    const float* rvar  = (const float*)d_in[8];
    const float* W2l   = (const float*)d_in[9];
    const float* b2l   = (const float*)d_in[10];
    const float* W2r   = (const float*)d_in[11];
    float* out = (float*)d_out;

    int E = in_sizes[1] / 2;
    if (E > EMAX) E = EMAX;
    const int* src = ei;
    const int* dst = ei + E;

    cudaFuncSetAttribute(gemm1_kernel, cudaFuncAttributeMaxDynamicSharedMemorySize, GEMM1_SMEM);
    cudaFuncSetAttribute(gemm2_kernel, cudaFuncAttributeMaxDynamicSharedMemorySize, GEMM2_SMEM);

    int nBlk = (NN + 255) / 256;          // 391
    int eBlk = (E + 255) / 256;           // 6250
    int wBlk = (NN * 32 + 255) / 256;     // 12500
    int gBlk = (NN + 63) / 64;            // 1563

    // CSR build
    zero_cnt_kernel<<<nBlk, 256>>>();
    hist_kernel<<<eBlk, 256>>>(dst, E);
    scan1_kernel<<<NB, 1024>>>();
    scan2_kernel<<<1, 128>>>();
    scan3_kernel<<<nBlk, 256>>>(E);
    fill_kernel<<<eBlk, 256>>>(src, dst, E);

    // pipeline
    agg1_kernel<<<wBlk, 256>>>(x);
    gemm1_kernel<<<gBlk, 256, GEMM1_SMEM>>>(x, W1l, b1l, W1r, gamma, beta, rmean, rvar);
    gemm2_kernel<<<gBlk, 256, GEMM2_SMEM>>>(W2l, W2r);
    agg2_kernel<<<wBlk, 256>>>(b2l, out);
}

// round 4
// speedup vs baseline: 2.9534x; 2.0457x over previous
#include <cuda_runtime.h>

#define NN 100000
#define EMAX 1600000
#define EPS 1e-5f
#define NB ((NN + 1023) >> 10)     // 98 scan blocks
#define GSTRIDE 88                 // smem row stride (floats): conflict-free LDS.64/STS.128

typedef unsigned int uint;

// ---- scratch (device globals) ----
__device__ __align__(256) float g_agg1[NN * 128];   // mean-aggregated x per dst
__device__ __align__(256) float g_h   [NN * 128];   // layer-1 output (post BN+ReLU)
__device__ __align__(256) float g_y2  [NN * 128];   // [ h@W2l^T (64) | h@W2r^T (64) ]
__device__ int g_cnt_i[NN];
__device__ int g_off[NN + 1];
__device__ int g_cur[NN];
__device__ int g_bsum[NB];
__device__ int g_ssrc[EMAX];

// ---- tf32 helpers ----
__device__ __forceinline__ uint to_tf32(float f) {
    uint u; asm("cvt.rna.tf32.f32 %0, %1;" : "=r"(u) : "f"(f)); return u;
}
__device__ __forceinline__ void mma8(float* d, const uint* a, const uint* b) {
    asm("mma.sync.aligned.m16n8k8.row.col.f32.tf32.tf32.f32 "
        "{%0,%1,%2,%3}, {%4,%5,%6,%7}, {%8,%9}, {%0,%1,%2,%3};"
        : "+f"(d[0]), "+f"(d[1]), "+f"(d[2]), "+f"(d[3])
        : "r"(a[0]), "r"(a[1]), "r"(a[2]), "r"(a[3]), "r"(b[0]), "r"(b[1]));
}

// ===========================================================================
// CSR build
// ===========================================================================
__global__ void zero_cnt_kernel() {
    int i = blockIdx.x * blockDim.x + threadIdx.x;
    if (i < NN) g_cnt_i[i] = 0;
}

__global__ void hist_kernel(const int* __restrict__ dst, int E) {
    int e = blockIdx.x * blockDim.x + threadIdx.x;
    if (e < E) atomicAdd(&g_cnt_i[dst[e]], 1);
}

__global__ void scan1_kernel() {
    __shared__ int sm[1024];
    int tid = threadIdx.x;
    int i = blockIdx.x * 1024 + tid;
    int v = (i < NN) ? g_cnt_i[i] : 0;
    sm[tid] = v;
    __syncthreads();
    for (int off = 1; off < 1024; off <<= 1) {
        int t = (tid >= off) ? sm[tid - off] : 0;
        __syncthreads();
        sm[tid] += t;
        __syncthreads();
    }
    if (i < NN) g_off[i] = sm[tid] - v;
    if (tid == 1023) g_bsum[blockIdx.x] = sm[1023];
}

__global__ void scan2_kernel() {
    __shared__ int sm[128];
    int tid = threadIdx.x;
    int v = (tid < NB) ? g_bsum[tid] : 0;
    sm[tid] = v;
    __syncthreads();
    for (int off = 1; off < 128; off <<= 1) {
        int t = (tid >= off) ? sm[tid - off] : 0;
        __syncthreads();
        sm[tid] += t;
        __syncthreads();
    }
    if (tid < NB) g_bsum[tid] = sm[tid] - v;
}

__global__ void scan3_kernel(int E) {
    int i = blockIdx.x * blockDim.x + threadIdx.x;
    if (i < NN) {
        int o = g_off[i] + g_bsum[i >> 10];
        g_off[i] = o;
        g_cur[i] = o;
    }
    if (i == 0) g_off[NN] = E;
}

__global__ void fill_kernel(const int* __restrict__ src,
                            const int* __restrict__ dst, int E) {
    int e = blockIdx.x * blockDim.x + threadIdx.x;
    if (e >= E) return;
    int p = atomicAdd(&g_cur[dst[e]], 1);
    g_ssrc[p] = src[e];
}

// ===========================================================================
// agg1: warp per dst, gather x rows over CSR list, write MEAN (no atomics)
// ===========================================================================
__global__ void __launch_bounds__(256) agg1_kernel(const float* __restrict__ x) {
    int w = (blockIdx.x * 256 + threadIdx.x) >> 5;
    if (w >= NN) return;
    int lane = threadIdx.x & 31;
    int beg = g_off[w], end = g_off[w + 1];
    float ax = 0.f, ay = 0.f, az = 0.f, aw = 0.f;
    int e = beg;
    for (; e + 2 <= end; e += 2) {
        int s0 = __ldg(g_ssrc + e);
        int s1 = __ldg(g_ssrc + e + 1);
        float4 v0 = __ldg((const float4*)x + (long long)s0 * 32 + lane);
        float4 v1 = __ldg((const float4*)x + (long long)s1 * 32 + lane);
        ax += v0.x; ay += v0.y; az += v0.z; aw += v0.w;
        ax += v1.x; ay += v1.y; az += v1.z; aw += v1.w;
    }
    if (e < end) {
        int s0 = __ldg(g_ssrc + e);
        float4 v0 = __ldg((const float4*)x + (long long)s0 * 32 + lane);
        ax += v0.x; ay += v0.y; az += v0.z; aw += v0.w;
    }
    float inv = 1.f / (float)max(end - beg, 1);
    float4 o = make_float4(ax * inv, ay * inv, az * inv, aw * inv);
    *((float4*)(g_agg1 + (long long)w * 128 + lane * 4)) = o;
}

// ===========================================================================
// agg2 + epilogue fused: out[d] = mean_agg(y2l) + b2l + y2r[d]
// ===========================================================================
__global__ void __launch_bounds__(256) agg2_kernel(const float* __restrict__ b2l,
                                                   float* __restrict__ out) {
    int w = (blockIdx.x * 256 + threadIdx.x) >> 5;
    if (w >= NN) return;
    int lane = threadIdx.x & 31;
    int beg = g_off[w], end = g_off[w + 1];
    float ax = 0.f, ay = 0.f;
    int e = beg;
    for (; e + 2 <= end; e += 2) {
        int s0 = __ldg(g_ssrc + e);
        int s1 = __ldg(g_ssrc + e + 1);
        float2 v0 = *(const float2*)(g_y2 + (long long)s0 * 128 + lane * 2);
        float2 v1 = *(const float2*)(g_y2 + (long long)s1 * 128 + lane * 2);
        ax += v0.x + v1.x; ay += v0.y + v1.y;
    }
    if (e < end) {
        int s0 = __ldg(g_ssrc + e);
        float2 v0 = *(const float2*)(g_y2 + (long long)s0 * 128 + lane * 2);
        ax += v0.x; ay += v0.y;
    }
    float inv = 1.f / (float)max(end - beg, 1);
    int j = lane * 2;
    float2 yr = *(const float2*)(g_y2 + (long long)w * 128 + 64 + j);
    float2 o = make_float2(ax * inv + __ldg(b2l + j)     + yr.x,
                           ay * inv + __ldg(b2l + j + 1) + yr.y);
    *(float2*)(out + (long long)w * 64 + j) = o;
}

// ===========================================================================
// tf32 tensor-core GEMMs. Block tile 128x128, 8 warps, warp tile 32x64.
// smem layout: per row, k8-groups stored in perm order [0,4,1,5,2,6,3,7]
// so every mma fragment load is one LDS.64; row stride 88 -> conflict-free.
// ===========================================================================
#define GEMM1_SMEM ((2 * 128 * GSTRIDE + 256) * 4)
#define GEMM2_SMEM ((2 * 128 * GSTRIDE) * 4)

// load a 128row x 64col fp32 tile from gmem (row stride 128) into perm-tf32 smem
__device__ __forceinline__ void load_tile(uint* S, const float* __restrict__ src,
                                          int row0, int rowMax, int kbase, int tid) {
    #pragma unroll
    for (int it = 0; it < 8; it++) {
        int u = it * 256 + tid;            // (row:7)(g:3)(h:1)
        int r = u >> 4;
        int g = (u >> 1) & 7;
        int h = u & 1;
        int grow = row0 + r;
        float2 va = make_float2(0.f, 0.f), vb = make_float2(0.f, 0.f);
        if (grow < rowMax) {
            const float* p = src + (long long)grow * 128 + kbase + g * 8 + 2 * h;
            va = __ldg((const float2*)p);
            vb = __ldg((const float2*)(p + 4));
        }
        uint4 o = make_uint4(to_tf32(va.x), to_tf32(vb.x), to_tf32(va.y), to_tf32(vb.y));
        *(uint4*)(S + r * GSTRIDE + g * 8 + 4 * h) = o;
    }
}

__global__ void __launch_bounds__(256, 2) gemm1_kernel(
    const float* __restrict__ x, const float* __restrict__ W1l,
    const float* __restrict__ b1l, const float* __restrict__ W1r,
    const float* __restrict__ gamma, const float* __restrict__ beta,
    const float* __restrict__ rmean, const float* __restrict__ rvar)
{
    extern __shared__ uint smu[];
    uint* As = smu;                       // [128][GSTRIDE]
    uint* Ws = smu + 128 * GSTRIDE;       // [128][GSTRIDE]
    float* gp   = (float*)(smu + 2 * 128 * GSTRIDE);  // [128]
    float* bias = gp + 128;                            // [128]

    int tid = threadIdx.x;
    int g0 = blockIdx.x * 128;

    if (tid < 128) {
        float g = gamma[tid] * rsqrtf(rvar[tid] + EPS);
        gp[tid] = g;
        bias[tid] = (b1l[tid] - rmean[tid]) * g + beta[tid];
    }
    __syncthreads();

    int lane = tid & 31, wid = tid >> 5;
    int warpM = wid >> 1, warpN = wid & 1;
    int fr = lane >> 2, cc = lane & 3;

    float acc[2][8][4];
    #pragma unroll
    for (int i = 0; i < 2; i++)
        #pragma unroll
        for (int j = 0; j < 8; j++)
            #pragma unroll
            for (int q = 0; q < 4; q++) acc[i][j][q] = 0.f;

    #pragma unroll
    for (int ch = 0; ch < 4; ch++) {
        const float* Asrc = (ch < 2) ? g_agg1 : x;
        const float* Wsrc = (ch < 2) ? W1l : W1r;
        int kbase = (ch & 1) * 64;

        // W tile: Ws[n][k'] = Wsrc[n][kbase+k] * gp[n]
        #pragma unroll
        for (int it = 0; it < 8; it++) {
            int u = it * 256 + tid;
            int n = u >> 4;
            int g = (u >> 1) & 7;
            int h = u & 1;
            const float* p = Wsrc + n * 128 + kbase + g * 8 + 2 * h;
            float2 va = __ldg((const float2*)p);
            float2 vb = __ldg((const float2*)(p + 4));
            float s = gp[n];
            uint4 o = make_uint4(to_tf32(va.x * s), to_tf32(vb.x * s),
                                 to_tf32(va.y * s), to_tf32(vb.y * s));
            *(uint4*)(Ws + n * GSTRIDE + g * 8 + 4 * h) = o;
        }
        load_tile(As, Asrc, g0, NN, kbase, tid);
        __syncthreads();

        const uint* Ab = As + (warpM * 32 + fr) * GSTRIDE + 2 * cc;
        const uint* Bb = Ws + (warpN * 64 + fr) * GSTRIDE + 2 * cc;
        #pragma unroll
        for (int g = 0; g < 8; g++) {
            uint a[2][4];
            #pragma unroll
            for (int mt = 0; mt < 2; mt++) {
                uint2 p0 = *(const uint2*)(Ab + (mt * 16) * GSTRIDE + g * 8);
                uint2 p1 = *(const uint2*)(Ab + (mt * 16 + 8) * GSTRIDE + g * 8);
                a[mt][0] = p0.x; a[mt][1] = p1.x; a[mt][2] = p0.y; a[mt][3] = p1.y;
            }
            #pragma unroll
            for (int nt = 0; nt < 8; nt++) {
                uint2 q = *(const uint2*)(Bb + (nt * 8) * GSTRIDE + g * 8);
                uint b[2] = {q.x, q.y};
                mma8(acc[0][nt], a[0], b);
                mma8(acc[1][nt], a[1], b);
            }
        }
        __syncthreads();
    }

    // epilogue: + bias (BN folded), ReLU
    #pragma unroll
    for (int mt = 0; mt < 2; mt++) {
        int r0 = g0 + warpM * 32 + mt * 16 + fr;
        #pragma unroll
        for (int nt = 0; nt < 8; nt++) {
            int col = warpN * 64 + nt * 8 + 2 * cc;
            float b0 = bias[col], b1 = bias[col + 1];
            if (r0 < NN)
                *(float2*)(g_h + (long long)r0 * 128 + col) =
                    make_float2(fmaxf(acc[mt][nt][0] + b0, 0.f),
                                fmaxf(acc[mt][nt][1] + b1, 0.f));
            if (r0 + 8 < NN)
                *(float2*)(g_h + (long long)(r0 + 8) * 128 + col) =
                    make_float2(fmaxf(acc[mt][nt][2] + b0, 0.f),
                                fmaxf(acc[mt][nt][3] + b1, 0.f));
        }
    }
}

__global__ void __launch_bounds__(256, 2) gemm2_kernel(
    const float* __restrict__ W2l, const float* __restrict__ W2r)
{
    extern __shared__ uint smu[];
    uint* As = smu;
    uint* Ws = smu + 128 * GSTRIDE;

    int tid = threadIdx.x;
    int g0 = blockIdx.x * 128;

    int lane = tid & 31, wid = tid >> 5;
    int warpM = wid >> 1, warpN = wid & 1;
    int fr = lane >> 2, cc = lane & 3;

    float acc[2][8][4];
    #pragma unroll
    for (int i = 0; i < 2; i++)
        #pragma unroll
        for (int j = 0; j < 8; j++)
            #pragma unroll
            for (int q = 0; q < 4; q++) acc[i][j][q] = 0.f;

    #pragma unroll
    for (int ch = 0; ch < 2; ch++) {
        int kbase = ch * 64;
        // W tile: cols 0-63 from W2l, 64-127 from W2r
        #pragma unroll
        for (int it = 0; it < 8; it++) {
            int u = it * 256 + tid;
            int n = u >> 4;
            int g = (u >> 1) & 7;
            int h = u & 1;
            const float* Wsrc = (n < 64) ? (W2l + n * 128) : (W2r + (n - 64) * 128);
            const float* p = Wsrc + kbase + g * 8 + 2 * h;
            float2 va = __ldg((const float2*)p);
            float2 vb = __ldg((const float2*)(p + 4));
            uint4 o = make_uint4(to_tf32(va.x), to_tf32(vb.x), to_tf32(va.y), to_tf32(vb.y));
            *(uint4*)(Ws + n * GSTRIDE + g * 8 + 4 * h) = o;
        }
        load_tile(As, g_h, g0, NN, kbase, tid);
        __syncthreads();

        const uint* Ab = As + (warpM * 32 + fr) * GSTRIDE + 2 * cc;
        const uint* Bb = Ws + (warpN * 64 + fr) * GSTRIDE + 2 * cc;
        #pragma unroll
        for (int g = 0; g < 8; g++) {
            uint a[2][4];
            #pragma unroll
            for (int mt = 0; mt < 2; mt++) {
                uint2 p0 = *(const uint2*)(Ab + (mt * 16) * GSTRIDE + g * 8);
                uint2 p1 = *(const uint2*)(Ab + (mt * 16 + 8) * GSTRIDE + g * 8);
                a[mt][0] = p0.x; a[mt][1] = p1.x; a[mt][2] = p0.y; a[mt][3] = p1.y;
            }
            #pragma unroll
            for (int nt = 0; nt < 8; nt++) {
                uint2 q = *(const uint2*)(Bb + (nt * 8) * GSTRIDE + g * 8);
                uint b[2] = {q.x, q.y};
                mma8(acc[0][nt], a[0], b);
                mma8(acc[1][nt], a[1], b);
            }
        }
        __syncthreads();
    }

    #pragma unroll
    for (int mt = 0; mt < 2; mt++) {
        int r0 = g0 + warpM * 32 + mt * 16 + fr;
        #pragma unroll
        for (int nt = 0; nt < 8; nt++) {
            int col = warpN * 64 + nt * 8 + 2 * cc;
            if (r0 < NN)
                *(float2*)(g_y2 + (long long)r0 * 128 + col) =
                    make_float2(acc[mt][nt][0], acc[mt][nt][1]);
            if (r0 + 8 < NN)
                *(float2*)(g_y2 + (long long)(r0 + 8) * 128 + col) =
                    make_float2(acc[mt][nt][2], acc[mt][nt][3]);
        }
    }
}

// ===========================================================================
extern "C" void kernel_launch(void* const* d_in, const int* in_sizes, int n_in,
                              void* d_out, int out_size) {
    const float* x     = (const float*)d_in[0];
    const int*   ei    = (const int*)d_in[1];     // int32 (JAX x64 disabled)
    const float* W1l   = (const float*)d_in[2];
    const float* b1l   = (const float*)d_in[3];
    const float* W1r   = (const float*)d_in[4];
    const float* gamma = (const float*)d_in[5];
    const float* beta  = (const float*)d_in[6];
    const float* rmean = (const float*)d_in[7];
    const float* rvar  = (const float*)d_in[8];
    const float* W2l   = (const float*)d_in[9];
    const float* b2l   = (const float*)d_in[10];
    const float* W2r   = (const float*)d_in[11];
    float* out = (float*)d_out;

    int E = in_sizes[1] / 2;
    if (E > EMAX) E = EMAX;
    const int* src = ei;
    const int* dst = ei + E;

    cudaFuncSetAttribute(gemm1_kernel, cudaFuncAttributeMaxDynamicSharedMemorySize, GEMM1_SMEM);
    cudaFuncSetAttribute(gemm2_kernel, cudaFuncAttributeMaxDynamicSharedMemorySize, GEMM2_SMEM);

    int nBlk = (NN + 255) / 256;
    int eBlk = (E + 255) / 256;
    int wBlk = (NN * 32 + 255) / 256;
    int gBlk = (NN + 127) / 128;          // 782

    // CSR build
    zero_cnt_kernel<<<nBlk, 256>>>();
    hist_kernel<<<eBlk, 256>>>(dst, E);
    scan1_kernel<<<NB, 1024>>>();
    scan2_kernel<<<1, 128>>>();
    scan3_kernel<<<nBlk, 256>>>(E);
    fill_kernel<<<eBlk, 256>>>(src, dst, E);

    // pipeline
    agg1_kernel<<<wBlk, 256>>>(x);
    gemm1_kernel<<<gBlk, 256, GEMM1_SMEM>>>(x, W1l, b1l, W1r, gamma, beta, rmean, rvar);
    gemm2_kernel<<<gBlk, 256, GEMM2_SMEM>>>(W2l, W2r);
    agg2_kernel<<<wBlk, 256>>>(b2l, out);
}

// round 6
// speedup vs baseline: 2.9675x; 1.0048x over previous
#include <cuda_runtime.h>
#include <cuda_fp16.h>

#define NN 100000
#define EMAX 1600000
#define EPS 1e-5f
#define NB ((NN + 1023) >> 10)     // 98 scan blocks
#define GSTRIDE 88                 // smem row stride (floats): conflict-free LDS.64/STS.128

typedef unsigned int uint;

// ---- scratch (device globals) ----
__device__ __align__(256) float  g_agg1[NN * 128];   // mean-aggregated x per dst (fp32)
__device__ __align__(256) float  g_h   [NN * 128];   // layer-1 output (post BN+ReLU)
__device__ __align__(256) __half g_xh  [NN * 128];   // fp16 copy of x (agg1 gather)
__device__ __align__(256) __half g_y2l [NN * 64];    // h@W2l^T in fp16 (agg2 gather)
__device__ __align__(256) float  g_y2r [NN * 64];    // h@W2r^T in fp32 (self term)
__device__ int g_cnt_i[NN];
__device__ int g_off[NN + 1];
__device__ int g_cur[NN];
__device__ int g_bsum[NB];
__device__ int g_ssrc[EMAX];

// ---- tf32 helpers ----
__device__ __forceinline__ uint to_tf32(float f) {
    uint u; asm("cvt.rna.tf32.f32 %0, %1;" : "=r"(u) : "f"(f)); return u;
}
__device__ __forceinline__ void mma8(float* d, const uint* a, const uint* b) {
    asm("mma.sync.aligned.m16n8k8.row.col.f32.tf32.tf32.f32 "
        "{%0,%1,%2,%3}, {%4,%5,%6,%7}, {%8,%9}, {%0,%1,%2,%3};"
        : "+f"(d[0]), "+f"(d[1]), "+f"(d[2]), "+f"(d[3])
        : "r"(a[0]), "r"(a[1]), "r"(a[2]), "r"(a[3]), "r"(b[0]), "r"(b[1]));
}

// ===========================================================================
// x -> fp16 staging copy (8 floats per thread)
// ===========================================================================
__global__ void convx_kernel(const float* __restrict__ x) {
    int i = blockIdx.x * blockDim.x + threadIdx.x;
    if (i >= NN * 16) return;
    const float4* p = (const float4*)x + (long long)i * 2;
    float4 a = __ldg(p);
    float4 b = __ldg(p + 1);
    __half2 h0 = __floats2half2_rn(a.x, a.y);
    __half2 h1 = __floats2half2_rn(a.z, a.w);
    __half2 h2 = __floats2half2_rn(b.x, b.y);
    __half2 h3 = __floats2half2_rn(b.z, b.w);
    uint4 o;
    o.x = *(uint*)&h0; o.y = *(uint*)&h1; o.z = *(uint*)&h2; o.w = *(uint*)&h3;
    *((uint4*)g_xh + i) = o;
}

// ===========================================================================
// CSR build
// ===========================================================================
__global__ void zero_cnt_kernel() {
    int i = blockIdx.x * blockDim.x + threadIdx.x;
    if (i < NN) g_cnt_i[i] = 0;
}

__global__ void hist_kernel(const int* __restrict__ dst, int E) {
    int e = blockIdx.x * blockDim.x + threadIdx.x;
    if (e < E) atomicAdd(&g_cnt_i[dst[e]], 1);
}

__global__ void scan1_kernel() {
    __shared__ int sm[1024];
    int tid = threadIdx.x;
    int i = blockIdx.x * 1024 + tid;
    int v = (i < NN) ? g_cnt_i[i] : 0;
    sm[tid] = v;
    __syncthreads();
    for (int off = 1; off < 1024; off <<= 1) {
        int t = (tid >= off) ? sm[tid - off] : 0;
        __syncthreads();
        sm[tid] += t;
        __syncthreads();
    }
    if (i < NN) g_off[i] = sm[tid] - v;
    if (tid == 1023) g_bsum[blockIdx.x] = sm[1023];
}

__global__ void scan2_kernel() {
    __shared__ int sm[128];
    int tid = threadIdx.x;
    int v = (tid < NB) ? g_bsum[tid] : 0;
    sm[tid] = v;
    __syncthreads();
    for (int off = 1; off < 128; off <<= 1) {
        int t = (tid >= off) ? sm[tid - off] : 0;
        __syncthreads();
        sm[tid] += t;
        __syncthreads();
    }
    if (tid < NB) g_bsum[tid] = sm[tid] - v;
}

__global__ void scan3_kernel(int E) {
    int i = blockIdx.x * blockDim.x + threadIdx.x;
    if (i < NN) {
        int o = g_off[i] + g_bsum[i >> 10];
        g_off[i] = o;
        g_cur[i] = o;
    }
    if (i == 0) g_off[NN] = E;
}

__global__ void fill_kernel(const int* __restrict__ src,
                            const int* __restrict__ dst, int E) {
    int e = blockIdx.x * blockDim.x + threadIdx.x;
    if (e >= E) return;
    int p = atomicAdd(&g_cur[dst[e]], 1);
    g_ssrc[p] = src[e];
}

// ===========================================================================
// agg1: warp per dst, gather fp16 x rows over CSR, write MEAN in fp32
// lane covers halves [lane*4, lane*4+4) -> one uint2 (8B) per lane per edge
// ===========================================================================
__global__ void __launch_bounds__(256) agg1_kernel() {
    int w = (blockIdx.x * 256 + threadIdx.x) >> 5;
    if (w >= NN) return;
    int lane = threadIdx.x & 31;
    int beg = g_off[w], end = g_off[w + 1];
    float ax = 0.f, ay = 0.f, az = 0.f, aw = 0.f;
    const uint2* xh = (const uint2*)g_xh;
    int e = beg;
    for (; e + 2 <= end; e += 2) {
        int s0 = __ldg(g_ssrc + e);
        int s1 = __ldg(g_ssrc + e + 1);
        uint2 v0 = __ldg(xh + (long long)s0 * 32 + lane);
        uint2 v1 = __ldg(xh + (long long)s1 * 32 + lane);
        float2 a0 = __half22float2(*(__half2*)&v0.x);
        float2 b0 = __half22float2(*(__half2*)&v0.y);
        float2 a1 = __half22float2(*(__half2*)&v1.x);
        float2 b1 = __half22float2(*(__half2*)&v1.y);
        ax += a0.x + a1.x; ay += a0.y + a1.y;
        az += b0.x + b1.x; aw += b0.y + b1.y;
    }
    if (e < end) {
        int s0 = __ldg(g_ssrc + e);
        uint2 v0 = __ldg(xh + (long long)s0 * 32 + lane);
        float2 a0 = __half22float2(*(__half2*)&v0.x);
        float2 b0 = __half22float2(*(__half2*)&v0.y);
        ax += a0.x; ay += a0.y; az += b0.x; aw += b0.y;
    }
    float inv = 1.f / (float)max(end - beg, 1);
    float4 o = make_float4(ax * inv, ay * inv, az * inv, aw * inv);
    *((float4*)(g_agg1 + (long long)w * 128 + lane * 4)) = o;
}

// ===========================================================================
// agg2 + epilogue fused: out[d] = mean_agg(y2l fp16) + b2l + y2r[d]
// lane covers y2l cols [lane*2, lane*2+2) -> one uint (4B) per lane per edge
// ===========================================================================
__global__ void __launch_bounds__(256) agg2_kernel(const float* __restrict__ b2l,
                                                   float* __restrict__ out) {
    int w = (blockIdx.x * 256 + threadIdx.x) >> 5;
    if (w >= NN) return;
    int lane = threadIdx.x & 31;
    int beg = g_off[w], end = g_off[w + 1];
    float ax = 0.f, ay = 0.f;
    const uint* yl = (const uint*)g_y2l;
    int e = beg;
    for (; e + 2 <= end; e += 2) {
        int s0 = __ldg(g_ssrc + e);
        int s1 = __ldg(g_ssrc + e + 1);
        uint v0 = __ldg(yl + (long long)s0 * 32 + lane);
        uint v1 = __ldg(yl + (long long)s1 * 32 + lane);
        float2 f0 = __half22float2(*(__half2*)&v0);
        float2 f1 = __half22float2(*(__half2*)&v1);
        ax += f0.x + f1.x; ay += f0.y + f1.y;
    }
    if (e < end) {
        int s0 = __ldg(g_ssrc + e);
        uint v0 = __ldg(yl + (long long)s0 * 32 + lane);
        float2 f0 = __half22float2(*(__half2*)&v0);
        ax += f0.x; ay += f0.y;
    }
    float inv = 1.f / (float)max(end - beg, 1);
    int j = lane * 2;
    float2 yr = *(const float2*)(g_y2r + (long long)w * 64 + j);
    float2 o = make_float2(ax * inv + __ldg(b2l + j)     + yr.x,
                           ay * inv + __ldg(b2l + j + 1) + yr.y);
    *(float2*)(out + (long long)w * 64 + j) = o;
}

// ===========================================================================
// tf32 tensor-core GEMMs. Block tile 128x128, 8 warps, warp tile 32x64.
// ===========================================================================
#define GEMM1_SMEM ((2 * 128 * GSTRIDE + 256) * 4)
#define GEMM2_SMEM ((2 * 128 * GSTRIDE) * 4)

__device__ __forceinline__ void load_tile(uint* S, const float* __restrict__ src,
                                          int row0, int rowMax, int kbase, int tid) {
    #pragma unroll
    for (int it = 0; it < 8; it++) {
        int u = it * 256 + tid;            // (row:7)(g:3)(h:1)
        int r = u >> 4;
        int g = (u >> 1) & 7;
        int h = u & 1;
        int grow = row0 + r;
        float2 va = make_float2(0.f, 0.f), vb = make_float2(0.f, 0.f);
        if (grow < rowMax) {
            const float* p = src + (long long)grow * 128 + kbase + g * 8 + 2 * h;
            va = __ldg((const float2*)p);
            vb = __ldg((const float2*)(p + 4));
        }
        uint4 o = make_uint4(to_tf32(va.x), to_tf32(vb.x), to_tf32(va.y), to_tf32(vb.y));
        *(uint4*)(S + r * GSTRIDE + g * 8 + 4 * h) = o;
    }
}

__global__ void __launch_bounds__(256, 2) gemm1_kernel(
    const float* __restrict__ x, const float* __restrict__ W1l,
    const float* __restrict__ b1l, const float* __restrict__ W1r,
    const float* __restrict__ gamma, const float* __restrict__ beta,
    const float* __restrict__ rmean, const float* __restrict__ rvar)
{
    extern __shared__ uint smu[];
    uint* As = smu;                       // [128][GSTRIDE]
    uint* Ws = smu + 128 * GSTRIDE;       // [128][GSTRIDE]
    float* gp   = (float*)(smu + 2 * 128 * GSTRIDE);  // [128]
    float* bias = gp + 128;                            // [128]

    int tid = threadIdx.x;
    int g0 = blockIdx.x * 128;

    if (tid < 128) {
        float g = gamma[tid] * rsqrtf(rvar[tid] + EPS);
        gp[tid] = g;
        bias[tid] = (b1l[tid] - rmean[tid]) * g + beta[tid];
    }
    __syncthreads();

    int lane = tid & 31, wid = tid >> 5;
    int warpM = wid >> 1, warpN = wid & 1;
    int fr = lane >> 2, cc = lane & 3;

    float acc[2][8][4];
    #pragma unroll
    for (int i = 0; i < 2; i++)
        #pragma unroll
        for (int j = 0; j < 8; j++)
            #pragma unroll
            for (int q = 0; q < 4; q++) acc[i][j][q] = 0.f;

    #pragma unroll
    for (int ch = 0; ch < 4; ch++) {
        const float* Asrc = (ch < 2) ? g_agg1 : x;
        const float* Wsrc = (ch < 2) ? W1l : W1r;
        int kbase = (ch & 1) * 64;

        #pragma unroll
        for (int it = 0; it < 8; it++) {
            int u = it * 256 + tid;
            int n = u >> 4;
            int g = (u >> 1) & 7;
            int h = u & 1;
            const float* p = Wsrc + n * 128 + kbase + g * 8 + 2 * h;
            float2 va = __ldg((const float2*)p);
            float2 vb = __ldg((const float2*)(p + 4));
            float s = gp[n];
            uint4 o = make_uint4(to_tf32(va.x * s), to_tf32(vb.x * s),
                                 to_tf32(va.y * s), to_tf32(vb.y * s));
            *(uint4*)(Ws + n * GSTRIDE + g * 8 + 4 * h) = o;
        }
        load_tile(As, Asrc, g0, NN, kbase, tid);
        __syncthreads();

        const uint* Ab = As + (warpM * 32 + fr) * GSTRIDE + 2 * cc;
        const uint* Bb = Ws + (warpN * 64 + fr) * GSTRIDE + 2 * cc;
        #pragma unroll
        for (int g = 0; g < 8; g++) {
            uint a[2][4];
            #pragma unroll
            for (int mt = 0; mt < 2; mt++) {
                uint2 p0 = *(const uint2*)(Ab + (mt * 16) * GSTRIDE + g * 8);
                uint2 p1 = *(const uint2*)(Ab + (mt * 16 + 8) * GSTRIDE + g * 8);
                a[mt][0] = p0.x; a[mt][1] = p1.x; a[mt][2] = p0.y; a[mt][3] = p1.y;
            }
            #pragma unroll
            for (int nt = 0; nt < 8; nt++) {
                uint2 q = *(const uint2*)(Bb + (nt * 8) * GSTRIDE + g * 8);
                uint b[2] = {q.x, q.y};
                mma8(acc[0][nt], a[0], b);
                mma8(acc[1][nt], a[1], b);
            }
        }
        __syncthreads();
    }

    #pragma unroll
    for (int mt = 0; mt < 2; mt++) {
        int r0 = g0 + warpM * 32 + mt * 16 + fr;
        #pragma unroll
        for (int nt = 0; nt < 8; nt++) {
            int col = warpN * 64 + nt * 8 + 2 * cc;
            float b0 = bias[col], b1 = bias[col + 1];
            if (r0 < NN)
                *(float2*)(g_h + (long long)r0 * 128 + col) =
                    make_float2(fmaxf(acc[mt][nt][0] + b0, 0.f),
                                fmaxf(acc[mt][nt][1] + b1, 0.f));
            if (r0 + 8 < NN)
                *(float2*)(g_h + (long long)(r0 + 8) * 128 + col) =
                    make_float2(fmaxf(acc[mt][nt][2] + b0, 0.f),
                                fmaxf(acc[mt][nt][3] + b1, 0.f));
        }
    }
}

__global__ void __launch_bounds__(256, 2) gemm2_kernel(
    const float* __restrict__ W2l, const float* __restrict__ W2r)
{
    extern __shared__ uint smu[];
    uint* As = smu;
    uint* Ws = smu + 128 * GSTRIDE;

    int tid = threadIdx.x;
    int g0 = blockIdx.x * 128;

    int lane = tid & 31, wid = tid >> 5;
    int warpM = wid >> 1, warpN = wid & 1;
    int fr = lane >> 2, cc = lane & 3;

    float acc[2][8][4];
    #pragma unroll
    for (int i = 0; i < 2; i++)
        #pragma unroll
        for (int j = 0; j < 8; j++)
            #pragma unroll
            for (int q = 0; q < 4; q++) acc[i][j][q] = 0.f;

    #pragma unroll
    for (int ch = 0; ch < 2; ch++) {
        int kbase = ch * 64;
        #pragma unroll
        for (int it = 0; it < 8; it++) {
            int u = it * 256 + tid;
            int n = u >> 4;
            int g = (u >> 1) & 7;
            int h = u & 1;
            const float* Wsrc = (n < 64) ? (W2l + n * 128) : (W2r + (n - 64) * 128);
            const float* p = Wsrc + kbase + g * 8 + 2 * h;
            float2 va = __ldg((const float2*)p);
            float2 vb = __ldg((const float2*)(p + 4));
            uint4 o = make_uint4(to_tf32(va.x), to_tf32(vb.x), to_tf32(va.y), to_tf32(vb.y));
            *(uint4*)(Ws + n * GSTRIDE + g * 8 + 4 * h) = o;
        }
        load_tile(As, g_h, g0, NN, kbase, tid);
        __syncthreads();

        const uint* Ab = As + (warpM * 32 + fr) * GSTRIDE + 2 * cc;
        const uint* Bb = Ws + (warpN * 64 + fr) * GSTRIDE + 2 * cc;
        #pragma unroll
        for (int g = 0; g < 8; g++) {
            uint a[2][4];
            #pragma unroll
            for (int mt = 0; mt < 2; mt++) {
                uint2 p0 = *(const uint2*)(Ab + (mt * 16) * GSTRIDE + g * 8);
                uint2 p1 = *(const uint2*)(Ab + (mt * 16 + 8) * GSTRIDE + g * 8);
                a[mt][0] = p0.x; a[mt][1] = p1.x; a[mt][2] = p0.y; a[mt][3] = p1.y;
            }
            #pragma unroll
            for (int nt = 0; nt < 8; nt++) {
                uint2 q = *(const uint2*)(Bb + (nt * 8) * GSTRIDE + g * 8);
                uint b[2] = {q.x, q.y};
                mma8(acc[0][nt], a[0], b);
                mma8(acc[1][nt], a[1], b);
            }
        }
        __syncthreads();
    }

    // epilogue: warpN==0 -> y2l cols 0..63 as fp16; warpN==1 -> y2r fp32
    #pragma unroll
    for (int mt = 0; mt < 2; mt++) {
        int r0 = g0 + warpM * 32 + mt * 16 + fr;
        #pragma unroll
        for (int nt = 0; nt < 8; nt++) {
            int colL = nt * 8 + 2 * cc;           // 0..63 within half
            if (warpN == 0) {
                if (r0 < NN) {
                    __half2 h = __floats2half2_rn(acc[mt][nt][0], acc[mt][nt][1]);
                    *(__half2*)(g_y2l + (long long)r0 * 64 + colL) = h;
                }
                if (r0 + 8 < NN) {
                    __half2 h = __floats2half2_rn(acc[mt][nt][2], acc[mt][nt][3]);
                    *(__half2*)(g_y2l + (long long)(r0 + 8) * 64 + colL) = h;
                }
            } else {
                if (r0 < NN)
                    *(float2*)(g_y2r + (long long)r0 * 64 + colL) =
                        make_float2(acc[mt][nt][0], acc[mt][nt][1]);
                if (r0 + 8 < NN)
                    *(float2*)(g_y2r + (long long)(r0 + 8) * 64 + colL) =
                        make_float2(acc[mt][nt][2], acc[mt][nt][3]);
            }
        }
    }
}

// ===========================================================================
extern "C" void kernel_launch(void* const* d_in, const int* in_sizes, int n_in,
                              void* d_out, int out_size) {
    const float* x     = (const float*)d_in[0];
    const int*   ei    = (const int*)d_in[1];     // int32 (JAX x64 disabled)
    const float* W1l   = (const float*)d_in[2];
    const float* b1l   = (const float*)d_in[3];
    const float* W1r   = (const float*)d_in[4];
    const float* gamma = (const float*)d_in[5];
    const float* beta  = (const float*)d_in[6];
    const float* rmean = (const float*)d_in[7];
    const float* rvar  = (const float*)d_in[8];
    const float* W2l   = (const float*)d_in[9];
    const float* b2l   = (const float*)d_in[10];
    const float* W2r   = (const float*)d_in[11];
    float* out = (float*)d_out;

    int E = in_sizes[1] / 2;
    if (E > EMAX) E = EMAX;
    const int* src = ei;
    const int* dst = ei + E;

    cudaFuncSetAttribute(gemm1_kernel, cudaFuncAttributeMaxDynamicSharedMemorySize, GEMM1_SMEM);
    cudaFuncSetAttribute(gemm2_kernel, cudaFuncAttributeMaxDynamicSharedMemorySize, GEMM2_SMEM);

    int nBlk = (NN + 255) / 256;
    int eBlk = (E + 255) / 256;
    int wBlk = (NN * 32 + 255) / 256;
    int gBlk = (NN + 127) / 128;          // 782
    int cBlk = (NN * 16 + 255) / 256;     // convx

    // CSR build + fp16 staging
    zero_cnt_kernel<<<nBlk, 256>>>();
    convx_kernel<<<cBlk, 256>>>(x);
    hist_kernel<<<eBlk, 256>>>(dst, E);
    scan1_kernel<<<NB, 1024>>>();
    scan2_kernel<<<1, 128>>>();
    scan3_kernel<<<nBlk, 256>>>(E);
    fill_kernel<<<eBlk, 256>>>(src, dst, E);

    // pipeline
    agg1_kernel<<<wBlk, 256>>>();
    gemm1_kernel<<<gBlk, 256, GEMM1_SMEM>>>(x, W1l, b1l, W1r, gamma, beta, rmean, rvar);
    gemm2_kernel<<<gBlk, 256, GEMM2_SMEM>>>(W2l, W2r);
    agg2_kernel<<<wBlk, 256>>>(b2l, out);
}

// round 8
// speedup vs baseline: 3.9071x; 1.3166x over previous
#include <cuda_runtime.h>
#include <cuda_fp16.h>

#define NN 100000
#define EMAX 1600000
#define EPS 1e-5f
#define NB ((NN + 1023) >> 10)     // 98 scan blocks
#define GSTRIDE 88                 // smem row stride (uints): conflict-free LDS.64/STS.128

typedef unsigned int uint;

// ---- scratch (device globals) ----
// interleaved fp16 layout: per row 128 k-values = 8 groups x 8 uints (half2 each),
// group order [k01,k89,k23,k10-11,k45,k12-13,k67,k14-15]
__device__ __align__(256) uint   g_xh [NN * 64];   // x, fp16 interleaved
__device__ __align__(256) uint   g_ag1[NN * 64];   // mean-agg(x), fp16 interleaved
__device__ __align__(256) uint   g_h  [NN * 64];   // layer-1 out, fp16 interleaved
__device__ __align__(256) __half g_y2l[NN * 64];   // h@W2l^T, fp16 plain
__device__ __align__(256) float  g_y2r[NN * 64];   // h@W2r^T, fp32 plain
__device__ int g_cnt_i[NN];
__device__ int g_off[NN + 1];
__device__ int g_cur[NN];
__device__ int g_bsum[NB];
__device__ int g_ssrc[EMAX];

// ---- helpers ----
__device__ __forceinline__ uint h2u(float lo, float hi) {
    __half2 h = __floats2half2_rn(lo, hi);
    return *(uint*)&h;
}
__device__ __forceinline__ void mma16(float* d, const uint* a, const uint* b) {
    asm("mma.sync.aligned.m16n8k16.row.col.f32.f16.f16.f32 "
        "{%0,%1,%2,%3}, {%4,%5,%6,%7}, {%8,%9}, {%0,%1,%2,%3};"
        : "+f"(d[0]), "+f"(d[1]), "+f"(d[2]), "+f"(d[3])
        : "r"(a[0]), "r"(a[1]), "r"(a[2]), "r"(a[3]), "r"(b[0]), "r"(b[1]));
}

// ===========================================================================
// fused: zero hist counters + convert x -> interleaved fp16
// ===========================================================================
__global__ void zeroconv_kernel(const float* __restrict__ x) {
    int u = blockIdx.x * 256 + threadIdx.x;
    if (u < NN) g_cnt_i[u] = 0;
    if (u >= NN * 8) return;
    int row = u >> 3, g = u & 7;
    const float4* p = (const float4*)(x + row * 128 + g * 16);
    float4 a = __ldg(p);        // k0-3
    float4 b = __ldg(p + 1);    // k4-7
    float4 c = __ldg(p + 2);    // k8-11
    float4 d = __ldg(p + 3);    // k12-15
    uint4 o0 = make_uint4(h2u(a.x, a.y), h2u(c.x, c.y), h2u(a.z, a.w), h2u(c.z, c.w));
    uint4 o1 = make_uint4(h2u(b.x, b.y), h2u(d.x, d.y), h2u(b.z, b.w), h2u(d.z, d.w));
    uint4* q = (uint4*)(g_xh + row * 64 + g * 8);
    q[0] = o0; q[1] = o1;
}

// ===========================================================================
// CSR build
// ===========================================================================
__global__ void hist_kernel(const int* __restrict__ dst, int E) {
    int e = blockIdx.x * blockDim.x + threadIdx.x;
    if (e < E) atomicAdd(&g_cnt_i[dst[e]], 1);
}

__global__ void scan1_kernel() {
    __shared__ int sm[1024];
    int tid = threadIdx.x;
    int i = blockIdx.x * 1024 + tid;
    int v = (i < NN) ? g_cnt_i[i] : 0;
    sm[tid] = v;
    __syncthreads();
    for (int off = 1; off < 1024; off <<= 1) {
        int t = (tid >= off) ? sm[tid - off] : 0;
        __syncthreads();
        sm[tid] += t;
        __syncthreads();
    }
    if (i < NN) g_off[i] = sm[tid] - v;
    if (tid == 1023) g_bsum[blockIdx.x] = sm[1023];
}

// fused scan2+scan3: every block redundantly scans the 98 block sums
__global__ void scan23_kernel(int E) {
    __shared__ int sm[128];
    int tid = threadIdx.x;
    if (tid < 128) sm[tid] = (tid < NB) ? g_bsum[tid] : 0;
    __syncthreads();
    for (int off = 1; off < 128; off <<= 1) {
        int t = (tid < 128 && tid >= off) ? sm[tid - off] : 0;
        __syncthreads();
        if (tid < 128) sm[tid] += t;          // inclusive scan
        __syncthreads();
    }
    int i = blockIdx.x * blockDim.x + tid;
    if (i < NN) {
        int b = i >> 10;
        int o = g_off[i] + (b ? sm[b - 1] : 0);
        g_off[i] = o;
        g_cur[i] = o;
    }
    if (i == 0) g_off[NN] = E;
}

__global__ void fill_kernel(const int* __restrict__ src,
                            const int* __restrict__ dst, int E) {
    int e = blockIdx.x * blockDim.x + threadIdx.x;
    if (e >= E) return;
    int p = atomicAdd(&g_cur[dst[e]], 1);
    g_ssrc[p] = src[e];
}

// ===========================================================================
// agg1: warp per dst, gather interleaved fp16 x rows, write MEAN (interleaved
// fp16). Elementwise sum is permutation-invariant, so interleave flows through.
// ===========================================================================
__global__ void __launch_bounds__(256) agg1_kernel() {
    int w = (blockIdx.x * 256 + threadIdx.x) >> 5;
    if (w >= NN) return;
    int lane = threadIdx.x & 31;
    int beg = g_off[w], end = g_off[w + 1];
    float a0 = 0.f, a1 = 0.f, a2 = 0.f, a3 = 0.f;
    const uint2* xh = (const uint2*)g_xh;
    int e = beg;
    for (; e + 4 <= end; e += 4) {
        uint2 v0 = __ldg(xh + (long long)__ldg(g_ssrc + e)     * 32 + lane);
        uint2 v1 = __ldg(xh + (long long)__ldg(g_ssrc + e + 1) * 32 + lane);
        uint2 v2 = __ldg(xh + (long long)__ldg(g_ssrc + e + 2) * 32 + lane);
        uint2 v3 = __ldg(xh + (long long)__ldg(g_ssrc + e + 3) * 32 + lane);
        float2 f;
        f = __half22float2(*(__half2*)&v0.x); a0 += f.x; a1 += f.y;
        f = __half22float2(*(__half2*)&v0.y); a2 += f.x; a3 += f.y;
        f = __half22float2(*(__half2*)&v1.x); a0 += f.x; a1 += f.y;
        f = __half22float2(*(__half2*)&v1.y); a2 += f.x; a3 += f.y;
        f = __half22float2(*(__half2*)&v2.x); a0 += f.x; a1 += f.y;
        f = __half22float2(*(__half2*)&v2.y); a2 += f.x; a3 += f.y;
        f = __half22float2(*(__half2*)&v3.x); a0 += f.x; a1 += f.y;
        f = __half22float2(*(__half2*)&v3.y); a2 += f.x; a3 += f.y;
    }
    for (; e < end; e++) {
        uint2 v0 = __ldg(xh + (long long)__ldg(g_ssrc + e) * 32 + lane);
        float2 f;
        f = __half22float2(*(__half2*)&v0.x); a0 += f.x; a1 += f.y;
        f = __half22float2(*(__half2*)&v0.y); a2 += f.x; a3 += f.y;
    }
    float inv = 1.f / (float)max(end - beg, 1);
    uint2 o = make_uint2(h2u(a0 * inv, a1 * inv), h2u(a2 * inv, a3 * inv));
    ((uint2*)g_ag1)[w * 32 + lane] = o;
}

// ===========================================================================
// agg2 + epilogue fused: out[d] = mean_agg(y2l fp16) + b2l + y2r[d]
// ===========================================================================
__global__ void __launch_bounds__(256) agg2_kernel(const float* __restrict__ b2l,
                                                   float* __restrict__ out) {
    int w = (blockIdx.x * 256 + threadIdx.x) >> 5;
    if (w >= NN) return;
    int lane = threadIdx.x & 31;
    int beg = g_off[w], end = g_off[w + 1];
    float ax = 0.f, ay = 0.f;
    const uint* yl = (const uint*)g_y2l;
    int e = beg;
    for (; e + 4 <= end; e += 4) {
        uint v0 = __ldg(yl + (long long)__ldg(g_ssrc + e)     * 32 + lane);
        uint v1 = __ldg(yl + (long long)__ldg(g_ssrc + e + 1) * 32 + lane);
        uint v2 = __ldg(yl + (long long)__ldg(g_ssrc + e + 2) * 32 + lane);
        uint v3 = __ldg(yl + (long long)__ldg(g_ssrc + e + 3) * 32 + lane);
        float2 f;
        f = __half22float2(*(__half2*)&v0); ax += f.x; ay += f.y;
        f = __half22float2(*(__half2*)&v1); ax += f.x; ay += f.y;
        f = __half22float2(*(__half2*)&v2); ax += f.x; ay += f.y;
        f = __half22float2(*(__half2*)&v3); ax += f.x; ay += f.y;
    }
    for (; e < end; e++) {
        uint v0 = __ldg(yl + (long long)__ldg(g_ssrc + e) * 32 + lane);
        float2 f = __half22float2(*(__half2*)&v0);
        ax += f.x; ay += f.y;
    }
    float inv = 1.f / (float)max(end - beg, 1);
    int j = lane * 2;
    float2 yr = *(const float2*)(g_y2r + (long long)w * 64 + j);
    float2 o = make_float2(ax * inv + __ldg(b2l + j)     + yr.x,
                           ay * inv + __ldg(b2l + j + 1) + yr.y);
    *(float2*)(out + (long long)w * 64 + j) = o;
}

// ===========================================================================
// fp16 HMMA GEMMs. Block tile 128x128, 8 warps, warp tile 32x64, k-chunk 128.
// smem: 128 rows x GSTRIDE uints; per row 8 k16-groups x 8 uints (interleaved).
// Fragment loads are single LDS.64 at (row*GSTRIDE + g*8 + 2*cc).
// ===========================================================================
#define TILE_U (128 * GSTRIDE)
#define GEMM1_SMEM ((2 * TILE_U + 256) * 4)
#define GEMM2_SMEM ((2 * TILE_U) * 4)

// straight copy of a pre-interleaved fp16 tile (row-major, 64 uints/row)
__device__ __forceinline__ void copy_tile(uint* S, const uint* __restrict__ src,
                                          int g0, int tid) {
    #pragma unroll
    for (int it = 0; it < 8; it++) {
        int u = it * 256 + tid;
        int r = u >> 4, j = u & 15;
        int grow = g0 + r;
        uint4 v = make_uint4(0u, 0u, 0u, 0u);
        if (grow < NN) v = __ldg((const uint4*)(src + grow * 64) + j);
        *(uint4*)(S + r * GSTRIDE + j * 4) = v;
    }
}

// fp32 weight [128][128] -> interleaved fp16 tile, optional per-row scale
__device__ __forceinline__ void convw_tile(uint* S, const float* __restrict__ W0,
                                           const float* gp, int tid) {
    #pragma unroll
    for (int it = 0; it < 8; it++) {
        int u = it * 256 + tid;
        int n = u >> 4, g = (u >> 1) & 7, h = u & 1;
        const float* p = W0 + n * 128 + g * 16 + 4 * h;
        float4 A = __ldg((const float4*)p);        // k base+0..3
        float4 B = __ldg((const float4*)(p + 8));  // k base+8..11
        float s = gp ? gp[n] : 1.f;
        uint4 o = make_uint4(h2u(A.x * s, A.y * s), h2u(B.x * s, B.y * s),
                             h2u(A.z * s, A.w * s), h2u(B.z * s, B.w * s));
        *(uint4*)(S + n * GSTRIDE + g * 8 + 4 * h) = o;
    }
}

struct FAcc { float a[2][8][4]; };

__device__ __forceinline__ void mainloop_h(const uint* As, const uint* Ws,
                                           int warpM, int warpN, int fr, int cc,
                                           FAcc& acc) {
    const uint* Ab = As + (warpM * 32 + fr) * GSTRIDE + 2 * cc;
    const uint* Bb = Ws + (warpN * 64 + fr) * GSTRIDE + 2 * cc;
    #pragma unroll
    for (int g = 0; g < 8; g++) {
        uint a[2][4];
        #pragma unroll
        for (int mt = 0; mt < 2; mt++) {
            uint2 p0 = *(const uint2*)(Ab + (mt * 16) * GSTRIDE + g * 8);
            uint2 p1 = *(const uint2*)(Ab + (mt * 16 + 8) * GSTRIDE + g * 8);
            a[mt][0] = p0.x; a[mt][1] = p1.x; a[mt][2] = p0.y; a[mt][3] = p1.y;
        }
        #pragma unroll
        for (int nt = 0; nt < 8; nt++) {
            uint2 q = *(const uint2*)(Bb + (nt * 8) * GSTRIDE + g * 8);
            uint b[2] = {q.x, q.y};
            mma16(acc.a[0][nt], a[0], b);
            mma16(acc.a[1][nt], a[1], b);
        }
    }
}

__global__ void __launch_bounds__(256, 2) gemm1_kernel(
    const float* __restrict__ W1l, const float* __restrict__ b1l,
    const float* __restrict__ W1r,
    const float* __restrict__ gamma, const float* __restrict__ beta,
    const float* __restrict__ rmean, const float* __restrict__ rvar)
{
    extern __shared__ uint smu[];
    uint* As = smu;
    uint* Ws = smu + TILE_U;
    float* gp   = (float*)(smu + 2 * TILE_U);
    float* bias = gp + 128;

    int tid = threadIdx.x;
    int g0 = blockIdx.x * 128;

    if (tid < 128) {
        float g = gamma[tid] * rsqrtf(rvar[tid] + EPS);
        gp[tid] = g;
        bias[tid] = (b1l[tid] - rmean[tid]) * g + beta[tid];
    }
    __syncthreads();

    int lane = tid & 31, wid = tid >> 5;
    int warpM = wid >> 1, warpN = wid & 1;
    int fr = lane >> 2, cc = lane & 3;

    FAcc acc;
    #pragma unroll
    for (int i = 0; i < 2; i++)
        #pragma unroll
        for (int j = 0; j < 8; j++)
            #pragma unroll
            for (int q = 0; q < 4; q++) acc.a[i][j][q] = 0.f;

    // chunk 0: mean-agg @ (W1l * gp)^T ; chunk 1: x @ (W1r * gp)^T
    #pragma unroll
    for (int ch = 0; ch < 2; ch++) {
        convw_tile(Ws, ch ? W1r : W1l, gp, tid);
        copy_tile(As, ch ? g_xh : g_ag1, g0, tid);
        __syncthreads();
        mainloop_h(As, Ws, warpM, warpN, fr, cc, acc);
        __syncthreads();
    }

    // epilogue: + bias, ReLU, store interleaved fp16 g_h
    #pragma unroll
    for (int mt = 0; mt < 2; mt++) {
        int r0 = g0 + warpM * 32 + mt * 16 + fr;
        #pragma unroll
        for (int nt = 0; nt < 8; nt++) {
            int col = warpN * 64 + nt * 8 + 2 * cc;     // even
            int t4 = (col & 15) >> 1;
            int j = (t4 < 4) ? 2 * t4 : 2 * (t4 - 4) + 1;
            int uidx = (col >> 4) * 8 + j;
            float b0 = bias[col], b1 = bias[col + 1];
            if (r0 < NN)
                g_h[r0 * 64 + uidx] = h2u(fmaxf(acc.a[mt][nt][0] + b0, 0.f),
                                          fmaxf(acc.a[mt][nt][1] + b1, 0.f));
            if (r0 + 8 < NN)
                g_h[(r0 + 8) * 64 + uidx] = h2u(fmaxf(acc.a[mt][nt][2] + b0, 0.f),
                                                fmaxf(acc.a[mt][nt][3] + b1, 0.f));
        }
    }
}

__global__ void __launch_bounds__(256, 2) gemm2_kernel(
    const float* __restrict__ W2l, const float* __restrict__ W2r)
{
    extern __shared__ uint smu[];
    uint* As = smu;
    uint* Ws = smu + TILE_U;

    int tid = threadIdx.x;
    int g0 = blockIdx.x * 128;

    int lane = tid & 31, wid = tid >> 5;
    int warpM = wid >> 1, warpN = wid & 1;
    int fr = lane >> 2, cc = lane & 3;

    // W tile: n 0..63 -> W2l, 64..127 -> W2r (no scale)
    #pragma unroll
    for (int it = 0; it < 8; it++) {
        int u = it * 256 + tid;
        int n = u >> 4, g = (u >> 1) & 7, h = u & 1;
        const float* Wsrc = (n < 64) ? (W2l + n * 128) : (W2r + (n - 64) * 128);
        const float* p = Wsrc + g * 16 + 4 * h;
        float4 A = __ldg((const float4*)p);
        float4 B = __ldg((const float4*)(p + 8));
        uint4 o = make_uint4(h2u(A.x, A.y), h2u(B.x, B.y),
                             h2u(A.z, A.w), h2u(B.z, B.w));
        *(uint4*)(Ws + n * GSTRIDE + g * 8 + 4 * h) = o;
    }
    copy_tile(As, g_h, g0, tid);
    __syncthreads();

    FAcc acc;
    #pragma unroll
    for (int i = 0; i < 2; i++)
        #pragma unroll
        for (int j = 0; j < 8; j++)
            #pragma unroll
            for (int q = 0; q < 4; q++) acc.a[i][j][q] = 0.f;

    mainloop_h(As, Ws, warpM, warpN, fr, cc, acc);

    // epilogue: warpN==0 -> y2l fp16 plain; warpN==1 -> y2r fp32 plain
    #pragma unroll
    for (int mt = 0; mt < 2; mt++) {
        int r0 = g0 + warpM * 32 + mt * 16 + fr;
        #pragma unroll
        for (int nt = 0; nt < 8; nt++) {
            int colL = nt * 8 + 2 * cc;
            if (warpN == 0) {
                if (r0 < NN)
                    *(__half2*)(g_y2l + (long long)r0 * 64 + colL) =
                        __floats2half2_rn(acc.a[mt][nt][0], acc.a[mt][nt][1]);
                if (r0 + 8 < NN)
                    *(__half2*)(g_y2l + (long long)(r0 + 8) * 64 + colL) =
                        __floats2half2_rn(acc.a[mt][nt][2], acc.a[mt][nt][3]);
            } else {
                if (r0 < NN)
                    *(float2*)(g_y2r + (long long)r0 * 64 + colL) =
                        make_float2(acc.a[mt][nt][0], acc.a[mt][nt][1]);
                if (r0 + 8 < NN)
                    *(float2*)(g_y2r + (long long)(r0 + 8) * 64 + colL) =
                        make_float2(acc.a[mt][nt][2], acc.a[mt][nt][3]);
            }
        }
    }
}

// ===========================================================================
extern "C" void kernel_launch(void* const* d_in, const int* in_sizes, int n_in,
                              void* d_out, int out_size) {
    const float* x     = (const float*)d_in[0];
    const int*   ei    = (const int*)d_in[1];     // int32 (JAX x64 disabled)
    const float* W1l   = (const float*)d_in[2];
    const float* b1l   = (const float*)d_in[3];
    const float* W1r   = (const float*)d_in[4];
    const float* gamma = (const float*)d_in[5];
    const float* beta  = (const float*)d_in[6];
    const float* rmean = (const float*)d_in[7];
    const float* rvar  = (const float*)d_in[8];
    const float* W2l   = (const float*)d_in[9];
    const float* b2l   = (const float*)d_in[10];
    const float* W2r   = (const float*)d_in[11];
    float* out = (float*)d_out;

    int E = in_sizes[1] / 2;
    if (E > EMAX) E = EMAX;
    const int* src = ei;
    const int* dst = ei + E;

    cudaFuncSetAttribute(gemm1_kernel, cudaFuncAttributeMaxDynamicSharedMemorySize, GEMM1_SMEM);
    cudaFuncSetAttribute(gemm2_kernel, cudaFuncAttributeMaxDynamicSharedMemorySize, GEMM2_SMEM);

    int zcBlk = (NN * 8 + 255) / 256;     // 3125
    int eBlk  = (E + 255) / 256;          // 6250
    int nBlk  = (NN + 255) / 256;         // 391
    int wBlk  = (NN * 32 + 255) / 256;    // 12500
    int gBlk  = (NN + 127) / 128;         // 782

    // CSR build + fp16 interleaved staging (9 launches total)
    zeroconv_kernel<<<zcBlk, 256>>>(x);
    hist_kernel<<<eBlk, 256>>>(dst, E);
    scan1_kernel<<<NB, 1024>>>();
    scan23_kernel<<<nBlk, 256>>>(E);
    fill_kernel<<<eBlk, 256>>>(src, dst, E);

    // pipeline
    agg1_kernel<<<wBlk, 256>>>();
    gemm1_kernel<<<gBlk, 256, GEMM1_SMEM>>>(W1l, b1l, W1r, gamma, beta, rmean, rvar);
    gemm2_kernel<<<gBlk, 256, GEMM2_SMEM>>>(W2l, W2r);
    agg2_kernel<<<wBlk, 256>>>(b2l, out);
}